// round 16
// baseline (speedup 1.0000x reference)
#include <cuda_runtime.h>
#include <cuda_fp16.h>
#include <math.h>

#define N_TOK 16384
#define D_MOD 1024
#define H_N   16
#define HK    64
#define M_F   256
#define FF_D  4096
#define S_LEN 4096
#define PHI_SCALE 0.35355339059327373f   // 64^-0.25
#define RSQRT_M  0.0625f                 // 1/sqrt(256)

// ---------------- scratch (device globals; allocation-free) ----------------
__device__ __half g_qk  [N_TOK * 2048];
__device__ __half g_v   [N_TOK * D_MOD];
__device__ __half g_xr  [N_TOK * D_MOD];
__device__ __half g_pq  [64 * S_LEN * M_F];
__device__ __half g_pk  [64 * S_LEN * M_F];
__device__ float  g_kv  [64 * M_F * HK];
__device__ float  g_z   [64 * M_F];
__device__ float  g_kvp [512 * 256 * 72];
__device__ __half g_attn[N_TOK * D_MOD];
__device__ float  g_y   [N_TOK * D_MOD];
__device__ __half g_x1  [N_TOK * D_MOD];
__device__ __half g_act [N_TOK * FF_D];
__device__ __half g_wqkvT[3 * D_MOD * D_MOD];
__device__ __half g_woT [D_MOD * D_MOD];
__device__ __half g_w1T [D_MOD * FF_D];
__device__ __half g_w2T [D_MOD * FF_D];

__device__ __forceinline__ unsigned smem_u32(const void* p) {
    unsigned a;
    asm("{ .reg .u64 t; cvta.to.shared.u64 t, %1; cvt.u32.u64 %0, t; }" : "=r"(a) : "l"(p));
    return a;
}
__device__ __forceinline__ unsigned pk2(const __half* p, int str) {
    unsigned lo = *(const unsigned short*)p;
    unsigned hi = *(const unsigned short*)(p + str);
    return lo | (hi << 16);
}
__device__ __forceinline__ void ldsm_x4(unsigned& r0, unsigned& r1,
                                        unsigned& r2, unsigned& r3, unsigned addr) {
    asm volatile("ldmatrix.sync.aligned.m8n8.x4.shared.b16 {%0,%1,%2,%3}, [%4];"
        : "=r"(r0), "=r"(r1), "=r"(r2), "=r"(r3) : "r"(addr));
}
__device__ __forceinline__ void ldsm_x4t(unsigned& r0, unsigned& r1,
                                         unsigned& r2, unsigned& r3, unsigned addr) {
    asm volatile("ldmatrix.sync.aligned.m8n8.x4.trans.shared.b16 {%0,%1,%2,%3}, [%4];"
        : "=r"(r0), "=r"(r1), "=r"(r2), "=r"(r3) : "r"(addr));
}

__device__ __forceinline__ void mma_f16(float* d, const unsigned* a, const unsigned* b) {
    asm volatile(
        "mma.sync.aligned.m16n8k16.row.col.f32.f16.f16.f32 "
        "{%0,%1,%2,%3}, {%4,%5,%6,%7}, {%8,%9}, {%0,%1,%2,%3};"
        : "+f"(d[0]), "+f"(d[1]), "+f"(d[2]), "+f"(d[3])
        : "r"(a[0]), "r"(a[1]), "r"(a[2]), "r"(a[3]), "r"(b[0]), "r"(b[1]));
}

#define CP16(dst, src) \
    asm volatile("cp.async.ca.shared.global [%0], [%1], 16;" :: "r"(dst), "l"(src))
#define CP_COMMIT() asm volatile("cp.async.commit_group;" ::: "memory")
#define CP_WAIT1()  asm volatile("cp.async.wait_group 1;" ::: "memory")
#define CP_WAIT0()  asm volatile("cp.async.wait_group 0;" ::: "memory")

// ---------------- fp16 warp-MMA GEMM (ldmatrix fragments) ----------------
#define HSTR   72
#define ROWB   144
#define TILEB  (128 * ROWB)              // 18432 bytes
#define STAGEB (2 * TILEB)               // 36864
#define SM_DYN (3 * STAGEB)              // 110592

template<int EPI>
__global__ __launch_bounds__(256, 2)
void tc_gemm(const __half* __restrict__ A, const __half* __restrict__ BT,
             const float* __restrict__ bias, const float* __restrict__ Rf,
             const __half* __restrict__ Rh, void* __restrict__ Cv,
             void* __restrict__ Cv2, int Kd, int NC)
{
    extern __shared__ char sm[];
    unsigned smu = smem_u32(sm);
    int tid = threadIdx.x, wid = tid >> 5, lane = tid & 31;
    int r0 = blockIdx.y * 128, c0 = blockIdx.x * 128;
    int wm = wid & 1, wn = wid >> 1;

    const __half* Ab = A + (size_t)r0 * Kd;
    const __half* Bb = BT + (size_t)c0 * Kd;

    int crow[4], cseg[4];
    unsigned cdst[4];
    #pragma unroll
    for (int i = 0; i < 4; i++) {
        int u = tid + 256 * i;
        crow[i] = u >> 3; cseg[i] = u & 7;
        cdst[i] = smu + (unsigned)(crow[i] * ROWB + cseg[i] * 16);
    }

    unsigned aoff = (unsigned)((lane & 15) * ROWB + (lane >> 4) * 16);
    unsigned boff = (unsigned)((((lane >> 4) * 8) + (lane & 7)) * ROWB +
                               ((lane >> 3) & 1) * 16);

    float acc[4][4][4];
    #pragma unroll
    for (int mi = 0; mi < 4; mi++)
        #pragma unroll
        for (int ni = 0; ni < 4; ni++)
            #pragma unroll
            for (int j = 0; j < 4; j++) acc[mi][ni][j] = 0.f;

    int nk = Kd >> 6;

    #pragma unroll
    for (int s = 0; s < 2; s++) {
        const __half* Ac = Ab + s * 64;
        const __half* Bc = Bb + s * 64;
        unsigned so = s * STAGEB;
        #pragma unroll
        for (int i = 0; i < 4; i++) {
            CP16(cdst[i] + so,         Ac + (size_t)crow[i] * Kd + cseg[i] * 8);
            CP16(cdst[i] + so + TILEB, Bc + (size_t)crow[i] * Kd + cseg[i] * 8);
        }
        CP_COMMIT();
    }

    int p = 0, pn = 2;
    for (int c = 0; c < nk; c++) {
        CP_WAIT1();
        __syncthreads();

        if (c + 2 < nk) {
            const __half* Ac = Ab + (c + 2) * 64;
            const __half* Bc = Bb + (c + 2) * 64;
            unsigned so = pn * STAGEB;
            #pragma unroll
            for (int i = 0; i < 4; i++) {
                CP16(cdst[i] + so,         Ac + (size_t)crow[i] * Kd + cseg[i] * 8);
                CP16(cdst[i] + so + TILEB, Bc + (size_t)crow[i] * Kd + cseg[i] * 8);
            }
        }
        CP_COMMIT();

        unsigned Asu = smu + p * STAGEB + (unsigned)(wm * 64) * ROWB + aoff;
        unsigned Bsu = smu + p * STAGEB + TILEB + (unsigned)(wn * 32) * ROWB + boff;

        #pragma unroll
        for (int ks = 0; ks < 4; ks++) {
            unsigned kb = ks * 32;
            unsigned afr[4][4], bfr[4][2];
            #pragma unroll
            for (int mi = 0; mi < 4; mi++)
                ldsm_x4(afr[mi][0], afr[mi][1], afr[mi][2], afr[mi][3],
                        Asu + mi * (16 * ROWB) + kb);
            #pragma unroll
            for (int pr = 0; pr < 2; pr++)
                ldsm_x4(bfr[2*pr][0], bfr[2*pr][1], bfr[2*pr+1][0], bfr[2*pr+1][1],
                        Bsu + pr * (16 * ROWB) + kb);
            #pragma unroll
            for (int mi = 0; mi < 4; mi++)
                #pragma unroll
                for (int ni = 0; ni < 4; ni++)
                    mma_f16(acc[mi][ni], afr[mi], bfr[ni]);
        }
        p = (p == 2) ? 0 : p + 1;
        pn = (pn == 2) ? 0 : pn + 1;
    }
    CP_WAIT0();
    __syncthreads();

    float* stage = (float*)sm;
    #pragma unroll
    for (int mi = 0; mi < 4; mi++)
        #pragma unroll
        for (int ni = 0; ni < 4; ni++) {
            int row = wm * 64 + mi * 16 + (lane >> 2);
            int col = wn * 32 + ni * 8 + (lane & 3) * 2;
            *(float2*)(stage + row * 132 + col) =
                make_float2(acc[mi][ni][0], acc[mi][ni][1]);
            *(float2*)(stage + (row + 8) * 132 + col) =
                make_float2(acc[mi][ni][2], acc[mi][ni][3]);
        }
    __syncthreads();

    #pragma unroll
    for (int i = 0; i < 16; i++) {
        int u = tid + 256 * i;
        int row = u >> 5, c4 = u & 31;
        float4 v = *(const float4*)(stage + row * 132 + c4 * 4);
        float vv[4] = {v.x, v.y, v.z, v.w};

        if (EPI == 5) {
            if (c0 < 2048) {
                size_t base = (size_t)(r0 + row) * 2048 + c0 + c4 * 4;
                __half2 p0 = __floats2half2_rn(vv[0], vv[1]);
                __half2 p1 = __floats2half2_rn(vv[2], vv[3]);
                uint2 w;
                w.x = *(unsigned*)&p0; w.y = *(unsigned*)&p1;
                *(uint2*)((__half*)Cv2 + base) = w;
            } else {
                size_t base = (size_t)(r0 + row) * 1024 + (c0 - 2048) + c4 * 4;
                __half2 p0 = __floats2half2_rn(vv[0], vv[1]);
                __half2 p1 = __floats2half2_rn(vv[2], vv[3]);
                uint2 w;
                w.x = *(unsigned*)&p0; w.y = *(unsigned*)&p1;
                *(uint2*)((__half*)Cv + base) = w;
            }
            continue;
        }

        size_t base = (size_t)(r0 + row) * NC + c0 + c4 * 4;
        #pragma unroll
        for (int j = 0; j < 4; j++) {
            int col = c0 + c4 * 4 + j;
            if (EPI == 1) vv[j] += Rf[base + j];
            else if (EPI == 2) {
                float t = vv[j] + bias[col];
                vv[j] = 0.5f * t * (1.0f + erff(t * 0.70710678118654752f));
            } else if (EPI == 3) vv[j] += bias[col] + __half2float(Rh[base + j]);
        }
        if (EPI == 0 || EPI == 2) {
            __half2 p0 = __floats2half2_rn(vv[0], vv[1]);
            __half2 p1 = __floats2half2_rn(vv[2], vv[3]);
            uint2 w;
            w.x = *(unsigned*)&p0; w.y = *(unsigned*)&p1;
            *(uint2*)((__half*)Cv + base) = w;
        } else {
            *(float4*)((float*)Cv + base) = make_float4(vv[0], vv[1], vv[2], vv[3]);
        }
    }
}

// ---------------- batched transpose + round to half (4x 1024x1024) ----------
__global__ void transpose4_k(const float* __restrict__ i0, const float* __restrict__ i1,
                             const float* __restrict__ i2, const float* __restrict__ i3,
                             __half* __restrict__ o0, __half* __restrict__ o1,
                             __half* __restrict__ o2, __half* __restrict__ o3)
{
    const float* in = (blockIdx.z == 0) ? i0 : (blockIdx.z == 1) ? i1 :
                      (blockIdx.z == 2) ? i2 : i3;
    __half* out = (blockIdx.z == 0) ? o0 : (blockIdx.z == 1) ? o1 :
                  (blockIdx.z == 2) ? o2 : o3;
    __shared__ float t[32][33];
    int x = blockIdx.x * 32 + threadIdx.x;
    int y = blockIdx.y * 32 + threadIdx.y;
    #pragma unroll
    for (int j = 0; j < 4; j++)
        t[threadIdx.y + j * 8][threadIdx.x] = in[(size_t)(y + j * 8) * 1024 + x];
    __syncthreads();
    int ox = blockIdx.y * 32 + threadIdx.x;
    int oy = blockIdx.x * 32 + threadIdx.y;
    #pragma unroll
    for (int j = 0; j < 4; j++)
        out[(size_t)(oy + j * 8) * 1024 + ox] = __float2half_rn(t[threadIdx.x][threadIdx.y + j * 8]);
}

__global__ void transpose_k(const float* __restrict__ in, __half* __restrict__ out,
                            int R, int Cc)
{
    __shared__ float t[32][33];
    int x = blockIdx.x * 32 + threadIdx.x;
    int y = blockIdx.y * 32 + threadIdx.y;
    #pragma unroll
    for (int j = 0; j < 4; j++)
        t[threadIdx.y + j * 8][threadIdx.x] = in[(size_t)(y + j * 8) * Cc + x];
    __syncthreads();
    int ox = blockIdx.y * 32 + threadIdx.x;
    int oy = blockIdx.x * 32 + threadIdx.y;
    #pragma unroll
    for (int j = 0; j < 4; j++)
        out[(size_t)(oy + j * 8) * R + ox] = __float2half_rn(t[threadIdx.x][threadIdx.y + j * 8]);
}

__global__ void cvt_half_kernel(const float* __restrict__ in, __half* __restrict__ out, int n8)
{
    int i = blockIdx.x * blockDim.x + threadIdx.x;
    if (i < n8) {
        float4 a = ((const float4*)in)[2 * i];
        float4 b = ((const float4*)in)[2 * i + 1];
        __half2 h0 = __floats2half2_rn(a.x, a.y);
        __half2 h1 = __floats2half2_rn(a.z, a.w);
        __half2 h2 = __floats2half2_rn(b.x, b.y);
        __half2 h3 = __floats2half2_rn(b.z, b.w);
        uint4 w;
        w.x = *(unsigned*)&h0; w.y = *(unsigned*)&h1;
        w.z = *(unsigned*)&h2; w.w = *(unsigned*)&h3;
        ((uint4*)out)[i] = w;
    }
}

// ---------------- tensorized FAVOR+ (fp16 MMA, ldmatrix), fused q+k ---------
#define PHSTR 72
#define PHROWB 144
#define PHI_A_OFF 0
#define PHI_B_OFF (128 * PHROWB)                    // 18432
#define PHI_STAGE_W 260
#define PHI_SQ_OFF  (128 * PHI_STAGE_W * 4)         // 133120
#define PHI_SM      (PHI_SQ_OFF + 128 * 4)          // 133632

__global__ __launch_bounds__(512, 1)
void phi_mma(const __half* __restrict__ qk, const float* __restrict__ omega,
             __half* __restrict__ pqd, __half* __restrict__ pkd)
{
    extern __shared__ char sm[];
    unsigned smu = smem_u32(sm);
    __half* As = (__half*)(sm + PHI_A_OFF);
    __half* Bs = (__half*)(sm + PHI_B_OFF);
    float* stage = (float*)sm;
    float* sqv   = (float*)(sm + PHI_SQ_OFF);

    int tid = threadIdx.x, wid = tid >> 5, lane = tid & 31;
    int outh = (blockIdx.x < 2048) ? 1 : 0;
    int rbase = (blockIdx.x & 2047) * 128;
    const __half* src = qk + (outh ? 0 : 1024);
    __half* dst = outh ? pqd : pkd;

    {
        int row = tid >> 2, qtr = tid & 3;
        int r = rbase + row, n = r >> 4, h = r & 15;
        const __half2* s2 = (const __half2*)(src + (size_t)n * 2048 + h * 64 + qtr * 16);
        unsigned outw[8];
        float ps = 0.f;
        #pragma unroll
        for (int j = 0; j < 8; j++) {
            float2 f = __half22float2(s2[j]);
            __half2 hh = __floats2half2_rn(f.x * PHI_SCALE, f.y * PHI_SCALE);
            float2 fr = __half22float2(hh);
            ps += fr.x * fr.x + fr.y * fr.y;
            outw[j] = *(unsigned*)&hh;
        }
        __half* dstA = As + row * PHSTR + qtr * 16;
        *(uint4*)(dstA)     = make_uint4(outw[0], outw[1], outw[2], outw[3]);
        *(uint4*)(dstA + 8) = make_uint4(outw[4], outw[5], outw[6], outw[7]);
        ps += __shfl_xor_sync(0xFFFFFFFFu, ps, 1);
        ps += __shfl_xor_sync(0xFFFFFFFFu, ps, 2);
        if (qtr == 0) sqv[row] = 0.5f * ps;
    }
    {
        int m = tid >> 1, hf = tid & 1;
        const float* orow = omega + m * 64 + hf * 32;
        #pragma unroll
        for (int j = 0; j < 4; j++) {
            float4 a = ((const float4*)orow)[2 * j];
            float4 b = ((const float4*)orow)[2 * j + 1];
            __half2 h0 = __floats2half2_rn(a.x, a.y);
            __half2 h1 = __floats2half2_rn(a.z, a.w);
            __half2 h2 = __floats2half2_rn(b.x, b.y);
            __half2 h3 = __floats2half2_rn(b.z, b.w);
            uint4 w;
            w.x = *(unsigned*)&h0; w.y = *(unsigned*)&h1;
            w.z = *(unsigned*)&h2; w.w = *(unsigned*)&h3;
            *(uint4*)(Bs + m * PHSTR + hf * 32 + j * 8) = w;
        }
    }
    __syncthreads();

    float acc[2][8][4];
    #pragma unroll
    for (int mi = 0; mi < 2; mi++)
        #pragma unroll
        for (int ni = 0; ni < 8; ni++)
            #pragma unroll
            for (int j = 0; j < 4; j++) acc[mi][ni][j] = 0.f;

    unsigned aoff = (unsigned)((lane & 15) * PHROWB + (lane >> 4) * 16);
    unsigned boff = (unsigned)((((lane >> 4) * 8) + (lane & 7)) * PHROWB +
                               ((lane >> 3) & 1) * 16);
    unsigned Asu = smu + PHI_A_OFF + (unsigned)((wid & 3) * 32) * PHROWB + aoff;
    unsigned Bsu = smu + PHI_B_OFF + (unsigned)((wid >> 2) * 64) * PHROWB + boff;

    #pragma unroll
    for (int ks = 0; ks < 4; ks++) {
        unsigned kb = ks * 32;
        unsigned afr[2][4], bfr[8][2];
        #pragma unroll
        for (int mi = 0; mi < 2; mi++)
            ldsm_x4(afr[mi][0], afr[mi][1], afr[mi][2], afr[mi][3],
                    Asu + mi * (16 * PHROWB) + kb);
        #pragma unroll
        for (int pr = 0; pr < 4; pr++)
            ldsm_x4(bfr[2*pr][0], bfr[2*pr][1], bfr[2*pr+1][0], bfr[2*pr+1][1],
                    Bsu + pr * (16 * PHROWB) + kb);
        #pragma unroll
        for (int mi = 0; mi < 2; mi++)
            #pragma unroll
            for (int ni = 0; ni < 8; ni++)
                mma_f16(acc[mi][ni], afr[mi], bfr[ni]);
    }
    __syncthreads();

    #pragma unroll
    for (int mi = 0; mi < 2; mi++)
        #pragma unroll
        for (int ni = 0; ni < 8; ni++) {
            int row = (wid & 3) * 32 + mi * 16 + (lane >> 2);
            int col = (wid >> 2) * 64 + ni * 8 + (lane & 3) * 2;
            *(float2*)(stage + row * PHI_STAGE_W + col) =
                make_float2(acc[mi][ni][0], acc[mi][ni][1]);
            *(float2*)(stage + (row + 8) * PHI_STAGE_W + col) =
                make_float2(acc[mi][ni][2], acc[mi][ni][3]);
        }
    __syncthreads();

    {
        int row = tid >> 2, seg = (tid & 3) * 64;
        const float* srow = stage + row * PHI_STAGE_W + seg;
        float mx = -1e30f;
        #pragma unroll
        for (int j = 0; j < 16; j++) {
            float4 v = ((const float4*)srow)[j];
            mx = fmaxf(mx, fmaxf(fmaxf(v.x, v.y), fmaxf(v.z, v.w)));
        }
        mx = fmaxf(mx, __shfl_xor_sync(0xFFFFFFFFu, mx, 1));
        mx = fmaxf(mx, __shfl_xor_sync(0xFFFFFFFFu, mx, 2));
        float sb = sqv[row] + mx;

        int r = rbase + row, n = r >> 4, h = r & 15;
        int b = n >> 12, s = n & 4095;
        size_t rowoff = (((size_t)(b * H_N + h)) * S_LEN + s) * M_F + seg;
        #pragma unroll
        for (int j = 0; j < 16; j++) {
            float4 v = ((const float4*)srow)[j];
            __half2 p0 = __floats2half2_rn(__expf(v.x - sb) * RSQRT_M + 1e-6f,
                                           __expf(v.y - sb) * RSQRT_M + 1e-6f);
            __half2 p1 = __floats2half2_rn(__expf(v.z - sb) * RSQRT_M + 1e-6f,
                                           __expf(v.w - sb) * RSQRT_M + 1e-6f);
            uint2 w;
            w.x = *(unsigned*)&p0; w.y = *(unsigned*)&p1;
            *(uint2*)(dst + rowoff + j * 4) = w;
        }
    }
}

// ---------------- fp16 kv: partial[blk][m][72] = pk^T @ [v | 1] --------------
// A fragments via ldmatrix.trans (s-major pk tiles); V via pk2.
#define KV_PSTR  264
#define KV_PSTRB (KV_PSTR * 2)
#define KV_VSTR  88
#define KV_PKB   (32 * KV_PSTRB)         // 16896
#define KV_VB    (32 * KV_VSTR * 2)      // 5632
#define KV_STAGE (KV_PKB + KV_VB)        // 22528
#define KV_SM    (2 * KV_STAGE)          // 45056

__global__ __launch_bounds__(256, 2)
void kv_mma(const __half* __restrict__ pk, const __half* __restrict__ v,
            float* __restrict__ partial)
{
    extern __shared__ char sm[];
    unsigned smu = smem_u32(sm);
    int tid = threadIdx.x, wid = tid >> 5, lane = tid & 31;
    int bh = blockIdx.x >> 3, chunk = blockIdx.x & 7;
    int b = bh >> 4, h = bh & 15;
    int s0 = chunk * 512;

    const __half* pkb = pk + ((size_t)bh * S_LEN + s0) * M_F;
    const __half* vb  = v + ((size_t)(b * S_LEN + s0)) * D_MOD + h * 64;

    for (int i = tid; i < 32 * 16 * 2; i += 256) {
        int st = i >> 9, r = (i & 511) >> 4, cc = (i & 15) + 64;
        ((__half*)(sm + st * KV_STAGE + KV_PKB))[r * KV_VSTR + cc] =
            (cc == 64) ? __float2half(1.f) : __float2half(0.f);
    }
    __syncthreads();

    auto issue_copy = [&](int cc, int st) {
        unsigned base = smu + st * KV_STAGE;
        #pragma unroll
        for (int i2 = 0; i2 < 4; i2++) {
            int j = tid + 256 * i2;
            int row = j >> 5, seg = j & 31;
            CP16(base + (unsigned)(row * KV_PSTRB + seg * 16),
                 pkb + (size_t)(cc * 32 + row) * M_F + seg * 8);
        }
        {
            int row = tid >> 3, seg = tid & 7;
            CP16(base + KV_PKB + (unsigned)(row * (KV_VSTR * 2) + seg * 16),
                 vb + (size_t)(cc * 32 + row) * D_MOD + seg * 8);
        }
    };

    float acc[4][5][4];
    #pragma unroll
    for (int mi = 0; mi < 4; mi++)
        #pragma unroll
        for (int ni = 0; ni < 5; ni++)
            #pragma unroll
            for (int j = 0; j < 4; j++) acc[mi][ni][j] = 0.f;

    issue_copy(0, 0); CP_COMMIT();
    issue_copy(1, 1); CP_COMMIT();

    int mbase = (wid & 3) * 64;
    int nbase = (wid >> 2) * 40 + (lane >> 2);

    // trans-ldmatrix lane offsets: g=lane>>3 (matrix), r=lane&7 (row-in-matrix)
    // row(k) = (g>>1)*8 + r ; col(m) offset = (g&1)*8 halves
    int lg = lane >> 3, lr = lane & 7;
    unsigned atoff = (unsigned)(((lg >> 1) * 8 + lr) * KV_PSTRB + (lg & 1) * 16);

    for (int c = 0; c < 16; c++) {
        int p = c & 1;
        CP_WAIT1();
        __syncthreads();

        unsigned Asu = smu + p * KV_STAGE + (unsigned)(mbase * 2) + atoff;
        const __half* Vs = (const __half*)(sm + p * KV_STAGE + KV_PKB);

        #pragma unroll
        for (int ks = 0; ks < 2; ks++) {
            int k0 = ks * 16 + (lane & 3) * 2;
            unsigned kb = (unsigned)(ks * 16) * KV_PSTRB;
            unsigned afr[4][4], bfr[5][2];
            #pragma unroll
            for (int mi = 0; mi < 4; mi++)
                ldsm_x4t(afr[mi][0], afr[mi][1], afr[mi][2], afr[mi][3],
                         Asu + kb + mi * 32);
            #pragma unroll
            for (int ni = 0; ni < 5; ni++) {
                int n = nbase + ni * 8;
                bfr[ni][0] = pk2(Vs + k0 * KV_VSTR + n, KV_VSTR);
                bfr[ni][1] = pk2(Vs + (k0 + 8) * KV_VSTR + n, KV_VSTR);
            }
            #pragma unroll
            for (int mi = 0; mi < 4; mi++)
                #pragma unroll
                for (int ni = 0; ni < 5; ni++)
                    mma_f16(acc[mi][ni], afr[mi], bfr[ni]);
        }
        __syncthreads();

        if (c + 2 < 16) issue_copy(c + 2, p);
        CP_COMMIT();
    }

    float* pb = partial + (size_t)blockIdx.x * (256 * 72);
    #pragma unroll
    for (int mi = 0; mi < 4; mi++)
        #pragma unroll
        for (int ni = 0; ni < 5; ni++) {
            int row = (wid & 3) * 64 + mi * 16 + (lane >> 2);
            int col = (wid >> 2) * 40 + ni * 8 + (lane & 3) * 2;
            if (col < 64) {
                *(float2*)(pb + row * 72 + col) =
                    make_float2(acc[mi][ni][0], acc[mi][ni][1]);
                *(float2*)(pb + (row + 8) * 72 + col) =
                    make_float2(acc[mi][ni][2], acc[mi][ni][3]);
            } else if (col == 64) {
                pb[row * 72 + 64] = acc[mi][ni][0];
                pb[(row + 8) * 72 + 64] = acc[mi][ni][2];
            }
        }
}

__global__ void kv_reduce(const float* __restrict__ partial,
                          float* __restrict__ kv, float* __restrict__ z)
{
    int bh = blockIdx.x;
    for (int j = threadIdx.x; j < 256 * 72; j += 256) {
        float s = 0.f;
        #pragma unroll
        for (int c = 0; c < 8; c++)
            s += partial[((size_t)(bh * 8 + c)) * (256 * 72) + j];
        int m = j / 72, k2 = j - m * 72;
        if (k2 < 64) kv[(size_t)bh * (M_F * HK) + m * 64 + k2] = s;
        else if (k2 == 64) z[bh * M_F + m] = s;
    }
}

// ---------------- fp16 num/den (ldmatrix): attn = (pq @ kv) / (pq @ z) ------
#define ND_BSTR  264
#define ND_BROWB (ND_BSTR * 2)
#define ND_B_OFF 0
#define ND_Z_OFF (64 * ND_BROWB)                 // 33792
#define ND_A_OFF (ND_Z_OFF + 1024)               // 34816
#define ND_SM    (ND_A_OFF + 2 * TILEB)          // 71680

__global__ __launch_bounds__(256, 2)
void numden_mma(const __half* __restrict__ pq, const float* __restrict__ kvg,
                const float* __restrict__ zg, __half* __restrict__ attn)
{
    extern __shared__ char sm[];
    unsigned smu = smem_u32(sm);
    __half* Bsf  = (__half*)(sm + ND_B_OFF);
    float* z_s   = (float*)(sm + ND_Z_OFF);
    float* den_s = (float*)(sm + ND_B_OFF);      // aliases Bs after MMA
    float* stage = (float*)(sm + ND_A_OFF);      // aliases As after MMA

    int bh = blockIdx.x >> 5;
    int chunk = blockIdx.x & 31;
    int b = bh >> 4, h = bh & 15;
    int tid = threadIdx.x, wid = tid >> 5, lane = tid & 31;
    int s0 = chunk * 128;

    const __half* pqb = pq + ((size_t)bh * S_LEN + s0) * M_F;

    int arow[4], aseg[4];
    unsigned adst[4];
    #pragma unroll
    for (int i = 0; i < 4; i++) {
        int u = tid + 256 * i;
        arow[i] = u >> 3; aseg[i] = u & 7;
        adst[i] = smu + ND_A_OFF + (unsigned)(arow[i] * ROWB + aseg[i] * 16);
    }

    #pragma unroll
    for (int s = 0; s < 2; s++) {
        const __half* Ac = pqb + s * 64;
        unsigned so = s * TILEB;
        #pragma unroll
        for (int i = 0; i < 4; i++)
            CP16(adst[i] + so, Ac + (size_t)arow[i] * M_F + aseg[i] * 8);
        CP_COMMIT();
    }

    {
        const float* kvb = kvg + (size_t)bh * (M_F * HK);
        for (int i = tid; i < M_F * HK; i += 256) {
            int m = i >> 6, k = i & 63;
            Bsf[k * ND_BSTR + m] = __float2half_rn(kvb[i]);
        }
        z_s[tid] = zg[bh * M_F + tid];
    }

    float acc[2][4][4];
    #pragma unroll
    for (int mi = 0; mi < 2; mi++)
        #pragma unroll
        for (int ni = 0; ni < 4; ni++)
            #pragma unroll
            for (int j = 0; j < 4; j++) acc[mi][ni][j] = 0.f;

    unsigned aoff = (unsigned)((lane & 15) * ROWB + (lane >> 4) * 16);
    unsigned boff = (unsigned)((((lane >> 4) * 8) + (lane & 7)) * ND_BROWB +
                               ((lane >> 3) & 1) * 16);
    unsigned Bsu0 = smu + ND_B_OFF + (unsigned)((wid >> 2) * 32) * ND_BROWB + boff;

    int drow = tid >> 1, dhf = tid & 1;
    float dp = 0.f;

    for (int c = 0; c < 4; c++) {
        int p = c & 1;
        CP_WAIT1();
        __syncthreads();

        const __half* As = (const __half*)(sm + ND_A_OFF + p * TILEB);
        unsigned Asu = smu + ND_A_OFF + p * TILEB +
                       (unsigned)((wid & 3) * 32) * ROWB + aoff;
        unsigned Bsu = Bsu0 + (unsigned)(c * 128);

        #pragma unroll
        for (int ks = 0; ks < 4; ks++) {
            unsigned kb = ks * 32;
            unsigned afr[2][4], bfr[4][2];
            #pragma unroll
            for (int mi = 0; mi < 2; mi++)
                ldsm_x4(afr[mi][0], afr[mi][1], afr[mi][2], afr[mi][3],
                        Asu + mi * (16 * ROWB) + kb);
            #pragma unroll
            for (int pr = 0; pr < 2; pr++)
                ldsm_x4(bfr[2*pr][0], bfr[2*pr][1], bfr[2*pr+1][0], bfr[2*pr+1][1],
                        Bsu + pr * (16 * ND_BROWB) + kb);
            #pragma unroll
            for (int mi = 0; mi < 2; mi++)
                #pragma unroll
                for (int ni = 0; ni < 4; ni++)
                    mma_f16(acc[mi][ni], afr[mi], bfr[ni]);
        }

        {
            const __half* ar = As + drow * HSTR + dhf * 32;
            const float* zr = z_s + c * 64 + dhf * 32;
            #pragma unroll
            for (int j = 0; j < 16; j++) {
                float2 f = __half22float2(*(const __half2*)(ar + 2 * j));
                dp += f.x * zr[2 * j] + f.y * zr[2 * j + 1];
            }
        }
        __syncthreads();

        if (c + 2 < 4) {
            const __half* Ac = pqb + (c + 2) * 64;
            unsigned so = p * TILEB;
            #pragma unroll
            for (int i = 0; i < 4; i++)
                CP16(adst[i] + so, Ac + (size_t)arow[i] * M_F + aseg[i] * 8);
        }
        CP_COMMIT();
    }
    CP_WAIT0();
    __syncthreads();

    #pragma unroll
    for (int mi = 0; mi < 2; mi++)
        #pragma unroll
        for (int ni = 0; ni < 4; ni++) {
            int row = (wid & 3) * 32 + mi * 16 + (lane >> 2);
            int col = (wid >> 2) * 32 + ni * 8 + (lane & 3) * 2;
            *(float2*)(stage + row * 68 + col) =
                make_float2(acc[mi][ni][0], acc[mi][ni][1]);
            *(float2*)(stage + (row + 8) * 68 + col) =
                make_float2(acc[mi][ni][2], acc[mi][ni][3]);
        }

    dp += __shfl_xor_sync(0xFFFFFFFFu, dp, 1);
    if (dhf == 0) den_s[drow] = dp;
    __syncthreads();

    #pragma unroll
    for (int i = 0; i < 8; i++) {
        int u = tid + 256 * i;
        int row = u >> 4, c4 = u & 15;
        float4 v = *(const float4*)(stage + row * 68 + c4 * 4);
        float rd = 1.0f / den_s[row];
        __half2 p0 = __floats2half2_rn(v.x * rd, v.y * rd);
        __half2 p1 = __floats2half2_rn(v.z * rd, v.w * rd);
        uint2 w;
        w.x = *(unsigned*)&p0; w.y = *(unsigned*)&p1;
        *(uint2*)(attn + ((size_t)(b * S_LEN + s0 + row)) * D_MOD + h * 64 + c4 * 4) = w;
    }
}

// ---------------- LayerNorm (OUTHALF: write half) ----------------
template<int OUTHALF>
__global__ void ln_kernel(const float* __restrict__ X, const float* __restrict__ g,
                          const float* __restrict__ bv, void* __restrict__ outv)
{
    int row = blockIdx.x, tid = threadIdx.x;
    float4 v = ((const float4*)(X + (size_t)row * D_MOD))[tid];
    float s = v.x + v.y + v.z + v.w;
    __shared__ float ws[8];
    #pragma unroll
    for (int o = 16; o; o >>= 1) s += __shfl_xor_sync(0xFFFFFFFFu, s, o);
    if ((tid & 31) == 0) ws[tid >> 5] = s;
    __syncthreads();
    float tot = 0.f;
    #pragma unroll
    for (int w = 0; w < 8; w++) tot += ws[w];
    float mu = tot * (1.f / 1024.f);
    float dx = v.x - mu, dy = v.y - mu, dz = v.z - mu, dw = v.w - mu;
    float sqvv = dx*dx + dy*dy + dz*dz + dw*dw;
    __syncthreads();
    #pragma unroll
    for (int o = 16; o; o >>= 1) sqvv += __shfl_xor_sync(0xFFFFFFFFu, sqvv, o);
    if ((tid & 31) == 0) ws[tid >> 5] = sqvv;
    __syncthreads();
    float tot2 = 0.f;
    #pragma unroll
    for (int w = 0; w < 8; w++) tot2 += ws[w];
    float rs = rsqrtf(tot2 * (1.f / 1024.f) + 1e-6f);
    float4 gg = ((const float4*)g)[tid];
    float4 bb = ((const float4*)bv)[tid];
    float o0 = dx*rs*gg.x + bb.x, o1 = dy*rs*gg.y + bb.y;
    float o2 = dz*rs*gg.z + bb.z, o3 = dw*rs*gg.w + bb.w;
    if (OUTHALF) {
        __half2 p0 = __floats2half2_rn(o0, o1);
        __half2 p1 = __floats2half2_rn(o2, o3);
        uint2 w;
        w.x = *(unsigned*)&p0; w.y = *(unsigned*)&p1;
        *(uint2*)((__half*)outv + (size_t)row * D_MOD + tid * 4) = w;
    } else {
        ((float4*)((float*)outv + (size_t)row * D_MOD))[tid] =
            make_float4(o0, o1, o2, o3);
    }
}

// ---------------- orchestration ----------------
extern "C" void kernel_launch(void* const* d_in, const int* in_sizes, int n_in,
                              void* d_out, int out_size)
{
    const float* x     = (const float*)d_in[0];
    const float* wq    = (const float*)d_in[1];
    const float* wk    = (const float*)d_in[2];
    const float* wv    = (const float*)d_in[3];
    const float* wo    = (const float*)d_in[4];
    const float* omega = (const float*)d_in[5];
    const float* ln1g  = (const float*)d_in[6];
    const float* ln1b  = (const float*)d_in[7];
    const float* w1    = (const float*)d_in[8];
    const float* b1    = (const float*)d_in[9];
    const float* w2    = (const float*)d_in[10];
    const float* b2    = (const float*)d_in[11];
    const float* ln2g  = (const float*)d_in[12];
    const float* ln2b  = (const float*)d_in[13];
    float* out = (float*)d_out;

    __half *qk, *v, *xr, *pq, *pk, *attn, *x1, *act;
    float *kv, *z, *kvp, *y;
    __half *wqkvT, *woT, *w1T, *w2T;
    cudaGetSymbolAddress((void**)&qk,   g_qk);
    cudaGetSymbolAddress((void**)&v,    g_v);
    cudaGetSymbolAddress((void**)&xr,   g_xr);
    cudaGetSymbolAddress((void**)&pq,   g_pq);
    cudaGetSymbolAddress((void**)&pk,   g_pk);
    cudaGetSymbolAddress((void**)&kv,   g_kv);
    cudaGetSymbolAddress((void**)&z,    g_z);
    cudaGetSymbolAddress((void**)&kvp,  g_kvp);
    cudaGetSymbolAddress((void**)&attn, g_attn);
    cudaGetSymbolAddress((void**)&y,    g_y);
    cudaGetSymbolAddress((void**)&x1,   g_x1);
    cudaGetSymbolAddress((void**)&act,  g_act);
    cudaGetSymbolAddress((void**)&wqkvT, g_wqkvT);
    cudaGetSymbolAddress((void**)&woT,  g_woT);
    cudaGetSymbolAddress((void**)&w1T,  g_w1T);
    cudaGetSymbolAddress((void**)&w2T,  g_w2T);

    cudaFuncSetAttribute(numden_mma, cudaFuncAttributeMaxDynamicSharedMemorySize, ND_SM);
    cudaFuncSetAttribute(phi_mma, cudaFuncAttributeMaxDynamicSharedMemorySize, PHI_SM);
    cudaFuncSetAttribute(kv_mma, cudaFuncAttributeMaxDynamicSharedMemorySize, KV_SM);
    cudaFuncSetAttribute(tc_gemm<1>, cudaFuncAttributeMaxDynamicSharedMemorySize, SM_DYN);
    cudaFuncSetAttribute(tc_gemm<2>, cudaFuncAttributeMaxDynamicSharedMemorySize, SM_DYN);
    cudaFuncSetAttribute(tc_gemm<3>, cudaFuncAttributeMaxDynamicSharedMemorySize, SM_DYN);
    cudaFuncSetAttribute(tc_gemm<5>, cudaFuncAttributeMaxDynamicSharedMemorySize, SM_DYN);

    dim3 tb(32, 8);
    transpose4_k<<<dim3(32, 32, 4), tb>>>(wq, wk, wv, wo,
        wqkvT, wqkvT + 1024 * 1024, wqkvT + 2 * 1024 * 1024, woT);
    transpose_k<<<dim3(128, 32),  tb>>>(w1, w1T, 1024, 4096);
    transpose_k<<<dim3(32, 128),  tb>>>(w2, w2T, 4096, 1024);
    cvt_half_kernel<<<(N_TOK * D_MOD / 8 + 255) / 256, 256>>>(x, xr, N_TOK * D_MOD / 8);

    dim3 gQKV(3072 / 128, N_TOK / 128);  // (24, 128)
    dim3 gD(D_MOD / 128, N_TOK / 128);   // (8, 128)
    dim3 gF(FF_D / 128, N_TOK / 128);    // (32, 128)

    tc_gemm<5><<<gQKV, 256, SM_DYN>>>(xr, wqkvT, nullptr, nullptr, nullptr,
                                      v, qk, D_MOD, 3072);

    phi_mma<<<4096, 512, PHI_SM>>>(qk, omega, pq, pk);

    kv_mma<<<512, 256, KV_SM>>>(pk, v, kvp);
    kv_reduce<<<64, 256>>>(kvp, kv, z);

    numden_mma<<<2048, 256, ND_SM>>>(pq, kv, z, attn);

    tc_gemm<1><<<gD, 256, SM_DYN>>>(attn, woT, nullptr, x, nullptr, y, nullptr,
                                    D_MOD, D_MOD);
    ln_kernel<1><<<N_TOK, 256>>>(y, ln1g, ln1b, x1);

    tc_gemm<2><<<gF, 256, SM_DYN>>>(x1, w1T, b1, nullptr, nullptr, act, nullptr,
                                    D_MOD, FF_D);
    tc_gemm<3><<<gD, 256, SM_DYN>>>(act, w2T, b2, nullptr, x1, y, nullptr,
                                    FF_D, D_MOD);
    ln_kernel<0><<<N_TOK, 256>>>(y, ln2g, ln2b, out);
}

// round 17
// speedup vs baseline: 1.0109x; 1.0109x over previous
#include <cuda_runtime.h>
#include <cuda_fp16.h>
#include <math.h>

#define N_TOK 16384
#define D_MOD 1024
#define H_N   16
#define HK    64
#define M_F   256
#define FF_D  4096
#define S_LEN 4096
#define PHI_SCALE 0.35355339059327373f   // 64^-0.25
#define RSQRT_M  0.0625f                 // 1/sqrt(256)

// ---------------- scratch (device globals; allocation-free) ----------------
__device__ __half g_qk  [N_TOK * 2048];
__device__ __half g_v   [N_TOK * D_MOD];
__device__ __half g_xr  [N_TOK * D_MOD];
__device__ __half g_pq  [64 * S_LEN * M_F];
__device__ __half g_pk  [64 * S_LEN * M_F];
__device__ float  g_kv  [64 * M_F * HK];
__device__ float  g_z   [64 * M_F];
__device__ float  g_kvp [256 * 256 * 72];
__device__ __half g_attn[N_TOK * D_MOD];
__device__ __half g_y   [N_TOK * D_MOD];
__device__ __half g_x1  [N_TOK * D_MOD];
__device__ __half g_act [N_TOK * FF_D];
__device__ __half g_wqkvT[3 * D_MOD * D_MOD];
__device__ __half g_woT [D_MOD * D_MOD];
__device__ __half g_w1T [D_MOD * FF_D];
__device__ __half g_w2T [D_MOD * FF_D];

__device__ __forceinline__ unsigned smem_u32(const void* p) {
    unsigned a;
    asm("{ .reg .u64 t; cvta.to.shared.u64 t, %1; cvt.u32.u64 %0, t; }" : "=r"(a) : "l"(p));
    return a;
}
__device__ __forceinline__ unsigned pk2(const __half* p, int str) {
    unsigned lo = *(const unsigned short*)p;
    unsigned hi = *(const unsigned short*)(p + str);
    return lo | (hi << 16);
}
__device__ __forceinline__ void ldsm_x4(unsigned& r0, unsigned& r1,
                                        unsigned& r2, unsigned& r3, unsigned addr) {
    asm volatile("ldmatrix.sync.aligned.m8n8.x4.shared.b16 {%0,%1,%2,%3}, [%4];"
        : "=r"(r0), "=r"(r1), "=r"(r2), "=r"(r3) : "r"(addr));
}
__device__ __forceinline__ void ldsm_x4t(unsigned& r0, unsigned& r1,
                                         unsigned& r2, unsigned& r3, unsigned addr) {
    asm volatile("ldmatrix.sync.aligned.m8n8.x4.trans.shared.b16 {%0,%1,%2,%3}, [%4];"
        : "=r"(r0), "=r"(r1), "=r"(r2), "=r"(r3) : "r"(addr));
}

__device__ __forceinline__ void mma_f16(float* d, const unsigned* a, const unsigned* b) {
    asm volatile(
        "mma.sync.aligned.m16n8k16.row.col.f32.f16.f16.f32 "
        "{%0,%1,%2,%3}, {%4,%5,%6,%7}, {%8,%9}, {%0,%1,%2,%3};"
        : "+f"(d[0]), "+f"(d[1]), "+f"(d[2]), "+f"(d[3])
        : "r"(a[0]), "r"(a[1]), "r"(a[2]), "r"(a[3]), "r"(b[0]), "r"(b[1]));
}

#define CP16(dst, src) \
    asm volatile("cp.async.ca.shared.global [%0], [%1], 16;" :: "r"(dst), "l"(src))
#define CP_COMMIT() asm volatile("cp.async.commit_group;" ::: "memory")
#define CP_WAIT1()  asm volatile("cp.async.wait_group 1;" ::: "memory")
#define CP_WAIT0()  asm volatile("cp.async.wait_group 0;" ::: "memory")

// ---------------- fp16 warp-MMA GEMM (ldmatrix fragments) ----------------
// EPI: 0 half-out, 1 +Rf(float) half-out, 2 gelu(x+bias) half-out,
//      3 +bias+Rh(half) half-out, 5 QKV route (qk half / v half)
#define HSTR   72
#define ROWB   144
#define TILEB  (128 * ROWB)              // 18432 bytes
#define STAGEB (2 * TILEB)               // 36864
#define SM_DYN (3 * STAGEB)              // 110592

template<int EPI>
__global__ __launch_bounds__(256, 2)
void tc_gemm(const __half* __restrict__ A, const __half* __restrict__ BT,
             const float* __restrict__ bias, const float* __restrict__ Rf,
             const __half* __restrict__ Rh, void* __restrict__ Cv,
             void* __restrict__ Cv2, int Kd, int NC)
{
    extern __shared__ char sm[];
    unsigned smu = smem_u32(sm);
    int tid = threadIdx.x, wid = tid >> 5, lane = tid & 31;
    int r0 = blockIdx.y * 128, c0 = blockIdx.x * 128;
    int wm = wid & 1, wn = wid >> 1;

    const __half* Ab = A + (size_t)r0 * Kd;
    const __half* Bb = BT + (size_t)c0 * Kd;

    int crow[4], cseg[4];
    unsigned cdst[4];
    #pragma unroll
    for (int i = 0; i < 4; i++) {
        int u = tid + 256 * i;
        crow[i] = u >> 3; cseg[i] = u & 7;
        cdst[i] = smu + (unsigned)(crow[i] * ROWB + cseg[i] * 16);
    }

    unsigned aoff = (unsigned)((lane & 15) * ROWB + (lane >> 4) * 16);
    unsigned boff = (unsigned)((((lane >> 4) * 8) + (lane & 7)) * ROWB +
                               ((lane >> 3) & 1) * 16);

    float acc[4][4][4];
    #pragma unroll
    for (int mi = 0; mi < 4; mi++)
        #pragma unroll
        for (int ni = 0; ni < 4; ni++)
            #pragma unroll
            for (int j = 0; j < 4; j++) acc[mi][ni][j] = 0.f;

    int nk = Kd >> 6;

    #pragma unroll
    for (int s = 0; s < 2; s++) {
        const __half* Ac = Ab + s * 64;
        const __half* Bc = Bb + s * 64;
        unsigned so = s * STAGEB;
        #pragma unroll
        for (int i = 0; i < 4; i++) {
            CP16(cdst[i] + so,         Ac + (size_t)crow[i] * Kd + cseg[i] * 8);
            CP16(cdst[i] + so + TILEB, Bc + (size_t)crow[i] * Kd + cseg[i] * 8);
        }
        CP_COMMIT();
    }

    int p = 0, pn = 2;
    for (int c = 0; c < nk; c++) {
        CP_WAIT1();
        __syncthreads();

        if (c + 2 < nk) {
            const __half* Ac = Ab + (c + 2) * 64;
            const __half* Bc = Bb + (c + 2) * 64;
            unsigned so = pn * STAGEB;
            #pragma unroll
            for (int i = 0; i < 4; i++) {
                CP16(cdst[i] + so,         Ac + (size_t)crow[i] * Kd + cseg[i] * 8);
                CP16(cdst[i] + so + TILEB, Bc + (size_t)crow[i] * Kd + cseg[i] * 8);
            }
        }
        CP_COMMIT();

        unsigned Asu = smu + p * STAGEB + (unsigned)(wm * 64) * ROWB + aoff;
        unsigned Bsu = smu + p * STAGEB + TILEB + (unsigned)(wn * 32) * ROWB + boff;

        #pragma unroll
        for (int ks = 0; ks < 4; ks++) {
            unsigned kb = ks * 32;
            unsigned afr[4][4], bfr[4][2];
            #pragma unroll
            for (int mi = 0; mi < 4; mi++)
                ldsm_x4(afr[mi][0], afr[mi][1], afr[mi][2], afr[mi][3],
                        Asu + mi * (16 * ROWB) + kb);
            #pragma unroll
            for (int pr = 0; pr < 2; pr++)
                ldsm_x4(bfr[2*pr][0], bfr[2*pr][1], bfr[2*pr+1][0], bfr[2*pr+1][1],
                        Bsu + pr * (16 * ROWB) + kb);
            #pragma unroll
            for (int mi = 0; mi < 4; mi++)
                #pragma unroll
                for (int ni = 0; ni < 4; ni++)
                    mma_f16(acc[mi][ni], afr[mi], bfr[ni]);
        }
        p = (p == 2) ? 0 : p + 1;
        pn = (pn == 2) ? 0 : pn + 1;
    }
    CP_WAIT0();
    __syncthreads();

    float* stage = (float*)sm;
    #pragma unroll
    for (int mi = 0; mi < 4; mi++)
        #pragma unroll
        for (int ni = 0; ni < 4; ni++) {
            int row = wm * 64 + mi * 16 + (lane >> 2);
            int col = wn * 32 + ni * 8 + (lane & 3) * 2;
            *(float2*)(stage + row * 132 + col) =
                make_float2(acc[mi][ni][0], acc[mi][ni][1]);
            *(float2*)(stage + (row + 8) * 132 + col) =
                make_float2(acc[mi][ni][2], acc[mi][ni][3]);
        }
    __syncthreads();

    #pragma unroll
    for (int i = 0; i < 16; i++) {
        int u = tid + 256 * i;
        int row = u >> 5, c4 = u & 31;
        float4 v = *(const float4*)(stage + row * 132 + c4 * 4);
        float vv[4] = {v.x, v.y, v.z, v.w};

        if (EPI == 5) {
            if (c0 < 2048) {
                size_t base = (size_t)(r0 + row) * 2048 + c0 + c4 * 4;
                __half2 p0 = __floats2half2_rn(vv[0], vv[1]);
                __half2 p1 = __floats2half2_rn(vv[2], vv[3]);
                uint2 w;
                w.x = *(unsigned*)&p0; w.y = *(unsigned*)&p1;
                *(uint2*)((__half*)Cv2 + base) = w;
            } else {
                size_t base = (size_t)(r0 + row) * 1024 + (c0 - 2048) + c4 * 4;
                __half2 p0 = __floats2half2_rn(vv[0], vv[1]);
                __half2 p1 = __floats2half2_rn(vv[2], vv[3]);
                uint2 w;
                w.x = *(unsigned*)&p0; w.y = *(unsigned*)&p1;
                *(uint2*)((__half*)Cv + base) = w;
            }
            continue;
        }

        size_t base = (size_t)(r0 + row) * NC + c0 + c4 * 4;
        #pragma unroll
        for (int j = 0; j < 4; j++) {
            int col = c0 + c4 * 4 + j;
            if (EPI == 1) vv[j] += Rf[base + j];
            else if (EPI == 2) {
                float t = vv[j] + bias[col];
                vv[j] = 0.5f * t * (1.0f + erff(t * 0.70710678118654752f));
            } else if (EPI == 3) vv[j] += bias[col] + __half2float(Rh[base + j]);
        }
        // all non-route epilogues emit half now (y is a half buffer)
        __half2 p0 = __floats2half2_rn(vv[0], vv[1]);
        __half2 p1 = __floats2half2_rn(vv[2], vv[3]);
        uint2 w;
        w.x = *(unsigned*)&p0; w.y = *(unsigned*)&p1;
        *(uint2*)((__half*)Cv + base) = w;
    }
}

// ---------------- batched transpose + round to half (4x 1024x1024) ----------
__global__ void transpose4_k(const float* __restrict__ i0, const float* __restrict__ i1,
                             const float* __restrict__ i2, const float* __restrict__ i3,
                             __half* __restrict__ o0, __half* __restrict__ o1,
                             __half* __restrict__ o2, __half* __restrict__ o3)
{
    const float* in = (blockIdx.z == 0) ? i0 : (blockIdx.z == 1) ? i1 :
                      (blockIdx.z == 2) ? i2 : i3;
    __half* out = (blockIdx.z == 0) ? o0 : (blockIdx.z == 1) ? o1 :
                  (blockIdx.z == 2) ? o2 : o3;
    __shared__ float t[32][33];
    int x = blockIdx.x * 32 + threadIdx.x;
    int y = blockIdx.y * 32 + threadIdx.y;
    #pragma unroll
    for (int j = 0; j < 4; j++)
        t[threadIdx.y + j * 8][threadIdx.x] = in[(size_t)(y + j * 8) * 1024 + x];
    __syncthreads();
    int ox = blockIdx.y * 32 + threadIdx.x;
    int oy = blockIdx.x * 32 + threadIdx.y;
    #pragma unroll
    for (int j = 0; j < 4; j++)
        out[(size_t)(oy + j * 8) * 1024 + ox] = __float2half_rn(t[threadIdx.x][threadIdx.y + j * 8]);
}

__global__ void transpose_k(const float* __restrict__ in, __half* __restrict__ out,
                            int R, int Cc)
{
    __shared__ float t[32][33];
    int x = blockIdx.x * 32 + threadIdx.x;
    int y = blockIdx.y * 32 + threadIdx.y;
    #pragma unroll
    for (int j = 0; j < 4; j++)
        t[threadIdx.y + j * 8][threadIdx.x] = in[(size_t)(y + j * 8) * Cc + x];
    __syncthreads();
    int ox = blockIdx.y * 32 + threadIdx.x;
    int oy = blockIdx.x * 32 + threadIdx.y;
    #pragma unroll
    for (int j = 0; j < 4; j++)
        out[(size_t)(oy + j * 8) * R + ox] = __float2half_rn(t[threadIdx.x][threadIdx.y + j * 8]);
}

__global__ void cvt_half_kernel(const float* __restrict__ in, __half* __restrict__ out, int n8)
{
    int i = blockIdx.x * blockDim.x + threadIdx.x;
    if (i < n8) {
        float4 a = ((const float4*)in)[2 * i];
        float4 b = ((const float4*)in)[2 * i + 1];
        __half2 h0 = __floats2half2_rn(a.x, a.y);
        __half2 h1 = __floats2half2_rn(a.z, a.w);
        __half2 h2 = __floats2half2_rn(b.x, b.y);
        __half2 h3 = __floats2half2_rn(b.z, b.w);
        uint4 w;
        w.x = *(unsigned*)&h0; w.y = *(unsigned*)&h1;
        w.z = *(unsigned*)&h2; w.w = *(unsigned*)&h3;
        ((uint4*)out)[i] = w;
    }
}

// ---------------- tensorized FAVOR+ (fp16 MMA, ldmatrix), fused q+k ---------
#define PHSTR 72
#define PHROWB 144
#define PHI_A_OFF 0
#define PHI_B_OFF (128 * PHROWB)                    // 18432
#define PHI_STAGE_W 260
#define PHI_SQ_OFF  (128 * PHI_STAGE_W * 4)         // 133120
#define PHI_SM      (PHI_SQ_OFF + 128 * 4)          // 133632

__global__ __launch_bounds__(512, 1)
void phi_mma(const __half* __restrict__ qk, const float* __restrict__ omega,
             __half* __restrict__ pqd, __half* __restrict__ pkd)
{
    extern __shared__ char sm[];
    unsigned smu = smem_u32(sm);
    __half* As = (__half*)(sm + PHI_A_OFF);
    __half* Bs = (__half*)(sm + PHI_B_OFF);
    float* stage = (float*)sm;
    float* sqv   = (float*)(sm + PHI_SQ_OFF);

    int tid = threadIdx.x, wid = tid >> 5, lane = tid & 31;
    int outh = (blockIdx.x < 2048) ? 1 : 0;
    int rbase = (blockIdx.x & 2047) * 128;
    const __half* src = qk + (outh ? 0 : 1024);
    __half* dst = outh ? pqd : pkd;

    {
        int row = tid >> 2, qtr = tid & 3;
        int r = rbase + row, n = r >> 4, h = r & 15;
        const __half2* s2 = (const __half2*)(src + (size_t)n * 2048 + h * 64 + qtr * 16);
        unsigned outw[8];
        float ps = 0.f;
        #pragma unroll
        for (int j = 0; j < 8; j++) {
            float2 f = __half22float2(s2[j]);
            __half2 hh = __floats2half2_rn(f.x * PHI_SCALE, f.y * PHI_SCALE);
            float2 fr = __half22float2(hh);
            ps += fr.x * fr.x + fr.y * fr.y;
            outw[j] = *(unsigned*)&hh;
        }
        __half* dstA = As + row * PHSTR + qtr * 16;
        *(uint4*)(dstA)     = make_uint4(outw[0], outw[1], outw[2], outw[3]);
        *(uint4*)(dstA + 8) = make_uint4(outw[4], outw[5], outw[6], outw[7]);
        ps += __shfl_xor_sync(0xFFFFFFFFu, ps, 1);
        ps += __shfl_xor_sync(0xFFFFFFFFu, ps, 2);
        if (qtr == 0) sqv[row] = 0.5f * ps;
    }
    {
        int m = tid >> 1, hf = tid & 1;
        const float* orow = omega + m * 64 + hf * 32;
        #pragma unroll
        for (int j = 0; j < 4; j++) {
            float4 a = ((const float4*)orow)[2 * j];
            float4 b = ((const float4*)orow)[2 * j + 1];
            __half2 h0 = __floats2half2_rn(a.x, a.y);
            __half2 h1 = __floats2half2_rn(a.z, a.w);
            __half2 h2 = __floats2half2_rn(b.x, b.y);
            __half2 h3 = __floats2half2_rn(b.z, b.w);
            uint4 w;
            w.x = *(unsigned*)&h0; w.y = *(unsigned*)&h1;
            w.z = *(unsigned*)&h2; w.w = *(unsigned*)&h3;
            *(uint4*)(Bs + m * PHSTR + hf * 32 + j * 8) = w;
        }
    }
    __syncthreads();

    float acc[2][8][4];
    #pragma unroll
    for (int mi = 0; mi < 2; mi++)
        #pragma unroll
        for (int ni = 0; ni < 8; ni++)
            #pragma unroll
            for (int j = 0; j < 4; j++) acc[mi][ni][j] = 0.f;

    unsigned aoff = (unsigned)((lane & 15) * PHROWB + (lane >> 4) * 16);
    unsigned boff = (unsigned)((((lane >> 4) * 8) + (lane & 7)) * PHROWB +
                               ((lane >> 3) & 1) * 16);
    unsigned Asu = smu + PHI_A_OFF + (unsigned)((wid & 3) * 32) * PHROWB + aoff;
    unsigned Bsu = smu + PHI_B_OFF + (unsigned)((wid >> 2) * 64) * PHROWB + boff;

    #pragma unroll
    for (int ks = 0; ks < 4; ks++) {
        unsigned kb = ks * 32;
        unsigned afr[2][4], bfr[8][2];
        #pragma unroll
        for (int mi = 0; mi < 2; mi++)
            ldsm_x4(afr[mi][0], afr[mi][1], afr[mi][2], afr[mi][3],
                    Asu + mi * (16 * PHROWB) + kb);
        #pragma unroll
        for (int pr = 0; pr < 4; pr++)
            ldsm_x4(bfr[2*pr][0], bfr[2*pr][1], bfr[2*pr+1][0], bfr[2*pr+1][1],
                    Bsu + pr * (16 * PHROWB) + kb);
        #pragma unroll
        for (int mi = 0; mi < 2; mi++)
            #pragma unroll
            for (int ni = 0; ni < 8; ni++)
                mma_f16(acc[mi][ni], afr[mi], bfr[ni]);
    }
    __syncthreads();

    #pragma unroll
    for (int mi = 0; mi < 2; mi++)
        #pragma unroll
        for (int ni = 0; ni < 8; ni++) {
            int row = (wid & 3) * 32 + mi * 16 + (lane >> 2);
            int col = (wid >> 2) * 64 + ni * 8 + (lane & 3) * 2;
            *(float2*)(stage + row * PHI_STAGE_W + col) =
                make_float2(acc[mi][ni][0], acc[mi][ni][1]);
            *(float2*)(stage + (row + 8) * PHI_STAGE_W + col) =
                make_float2(acc[mi][ni][2], acc[mi][ni][3]);
        }
    __syncthreads();

    {
        int row = tid >> 2, seg = (tid & 3) * 64;
        const float* srow = stage + row * PHI_STAGE_W + seg;
        float mx = -1e30f;
        #pragma unroll
        for (int j = 0; j < 16; j++) {
            float4 v = ((const float4*)srow)[j];
            mx = fmaxf(mx, fmaxf(fmaxf(v.x, v.y), fmaxf(v.z, v.w)));
        }
        mx = fmaxf(mx, __shfl_xor_sync(0xFFFFFFFFu, mx, 1));
        mx = fmaxf(mx, __shfl_xor_sync(0xFFFFFFFFu, mx, 2));
        float sb = sqv[row] + mx;

        int r = rbase + row, n = r >> 4, h = r & 15;
        int b = n >> 12, s = n & 4095;
        size_t rowoff = (((size_t)(b * H_N + h)) * S_LEN + s) * M_F + seg;
        #pragma unroll
        for (int j = 0; j < 16; j++) {
            float4 v = ((const float4*)srow)[j];
            __half2 p0 = __floats2half2_rn(__expf(v.x - sb) * RSQRT_M + 1e-6f,
                                           __expf(v.y - sb) * RSQRT_M + 1e-6f);
            __half2 p1 = __floats2half2_rn(__expf(v.z - sb) * RSQRT_M + 1e-6f,
                                           __expf(v.w - sb) * RSQRT_M + 1e-6f);
            uint2 w;
            w.x = *(unsigned*)&p0; w.y = *(unsigned*)&p1;
            *(uint2*)(dst + rowoff + j * 4) = w;
        }
    }
}

// ---------------- fp16 kv: partial[blk][m][72] = pk^T @ [v | 1] --------------
// grid = 64 bh x 4 s-chunks (chunk 1024) -> single wave of 296.
#define KV_PSTR  264
#define KV_PSTRB (KV_PSTR * 2)
#define KV_VSTR  88
#define KV_PKB   (32 * KV_PSTRB)         // 16896
#define KV_VB    (32 * KV_VSTR * 2)      // 5632
#define KV_STAGE (KV_PKB + KV_VB)        // 22528
#define KV_SM    (2 * KV_STAGE)          // 45056

__global__ __launch_bounds__(256, 2)
void kv_mma(const __half* __restrict__ pk, const __half* __restrict__ v,
            float* __restrict__ partial)
{
    extern __shared__ char sm[];
    unsigned smu = smem_u32(sm);
    int tid = threadIdx.x, wid = tid >> 5, lane = tid & 31;
    int bh = blockIdx.x >> 2, chunk = blockIdx.x & 3;
    int b = bh >> 4, h = bh & 15;
    int s0 = chunk * 1024;

    const __half* pkb = pk + ((size_t)bh * S_LEN + s0) * M_F;
    const __half* vb  = v + ((size_t)(b * S_LEN + s0)) * D_MOD + h * 64;

    for (int i = tid; i < 32 * 16 * 2; i += 256) {
        int st = i >> 9, r = (i & 511) >> 4, cc = (i & 15) + 64;
        ((__half*)(sm + st * KV_STAGE + KV_PKB))[r * KV_VSTR + cc] =
            (cc == 64) ? __float2half(1.f) : __float2half(0.f);
    }
    __syncthreads();

    auto issue_copy = [&](int cc, int st) {
        unsigned base = smu + st * KV_STAGE;
        #pragma unroll
        for (int i2 = 0; i2 < 4; i2++) {
            int j = tid + 256 * i2;
            int row = j >> 5, seg = j & 31;
            CP16(base + (unsigned)(row * KV_PSTRB + seg * 16),
                 pkb + (size_t)(cc * 32 + row) * M_F + seg * 8);
        }
        {
            int row = tid >> 3, seg = tid & 7;
            CP16(base + KV_PKB + (unsigned)(row * (KV_VSTR * 2) + seg * 16),
                 vb + (size_t)(cc * 32 + row) * D_MOD + seg * 8);
        }
    };

    float acc[4][5][4];
    #pragma unroll
    for (int mi = 0; mi < 4; mi++)
        #pragma unroll
        for (int ni = 0; ni < 5; ni++)
            #pragma unroll
            for (int j = 0; j < 4; j++) acc[mi][ni][j] = 0.f;

    issue_copy(0, 0); CP_COMMIT();
    issue_copy(1, 1); CP_COMMIT();

    int mbase = (wid & 3) * 64;
    int nbase = (wid >> 2) * 40 + (lane >> 2);

    int lg = lane >> 3, lr = lane & 7;
    unsigned atoff = (unsigned)(((lg >> 1) * 8 + lr) * KV_PSTRB + (lg & 1) * 16);

    for (int c = 0; c < 32; c++) {
        int p = c & 1;
        CP_WAIT1();
        __syncthreads();

        unsigned Asu = smu + p * KV_STAGE + (unsigned)(mbase * 2) + atoff;
        const __half* Vs = (const __half*)(sm + p * KV_STAGE + KV_PKB);

        #pragma unroll
        for (int ks = 0; ks < 2; ks++) {
            int k0 = ks * 16 + (lane & 3) * 2;
            unsigned kb = (unsigned)(ks * 16) * KV_PSTRB;
            unsigned afr[4][4], bfr[5][2];
            #pragma unroll
            for (int mi = 0; mi < 4; mi++)
                ldsm_x4t(afr[mi][0], afr[mi][1], afr[mi][2], afr[mi][3],
                         Asu + kb + mi * 32);
            #pragma unroll
            for (int ni = 0; ni < 5; ni++) {
                int n = nbase + ni * 8;
                bfr[ni][0] = pk2(Vs + k0 * KV_VSTR + n, KV_VSTR);
                bfr[ni][1] = pk2(Vs + (k0 + 8) * KV_VSTR + n, KV_VSTR);
            }
            #pragma unroll
            for (int mi = 0; mi < 4; mi++)
                #pragma unroll
                for (int ni = 0; ni < 5; ni++)
                    mma_f16(acc[mi][ni], afr[mi], bfr[ni]);
        }
        __syncthreads();

        if (c + 2 < 32) issue_copy(c + 2, p);
        CP_COMMIT();
    }

    float* pb = partial + (size_t)blockIdx.x * (256 * 72);
    #pragma unroll
    for (int mi = 0; mi < 4; mi++)
        #pragma unroll
        for (int ni = 0; ni < 5; ni++) {
            int row = (wid & 3) * 64 + mi * 16 + (lane >> 2);
            int col = (wid >> 2) * 40 + ni * 8 + (lane & 3) * 2;
            if (col < 64) {
                *(float2*)(pb + row * 72 + col) =
                    make_float2(acc[mi][ni][0], acc[mi][ni][1]);
                *(float2*)(pb + (row + 8) * 72 + col) =
                    make_float2(acc[mi][ni][2], acc[mi][ni][3]);
            } else if (col == 64) {
                pb[row * 72 + 64] = acc[mi][ni][0];
                pb[(row + 8) * 72 + 64] = acc[mi][ni][2];
            }
        }
}

__global__ void kv_reduce(const float* __restrict__ partial,
                          float* __restrict__ kv, float* __restrict__ z)
{
    int bh = blockIdx.x;
    for (int j = threadIdx.x; j < 256 * 72; j += 256) {
        float s = 0.f;
        #pragma unroll
        for (int c = 0; c < 4; c++)
            s += partial[((size_t)(bh * 4 + c)) * (256 * 72) + j];
        int m = j / 72, k2 = j - m * 72;
        if (k2 < 64) kv[(size_t)bh * (M_F * HK) + m * 64 + k2] = s;
        else if (k2 == 64) z[bh * M_F + m] = s;
    }
}

// ---------------- fp16 num/den (ldmatrix): attn = (pq @ kv) / (pq @ z) ------
#define ND_BSTR  264
#define ND_BROWB (ND_BSTR * 2)
#define ND_B_OFF 0
#define ND_Z_OFF (64 * ND_BROWB)                 // 33792
#define ND_A_OFF (ND_Z_OFF + 1024)               // 34816
#define ND_SM    (ND_A_OFF + 2 * TILEB)          // 71680

__global__ __launch_bounds__(256, 2)
void numden_mma(const __half* __restrict__ pq, const float* __restrict__ kvg,
                const float* __restrict__ zg, __half* __restrict__ attn)
{
    extern __shared__ char sm[];
    unsigned smu = smem_u32(sm);
    __half* Bsf  = (__half*)(sm + ND_B_OFF);
    float* z_s   = (float*)(sm + ND_Z_OFF);
    float* den_s = (float*)(sm + ND_B_OFF);
    float* stage = (float*)(sm + ND_A_OFF);

    int bh = blockIdx.x >> 5;
    int chunk = blockIdx.x & 31;
    int b = bh >> 4, h = bh & 15;
    int tid = threadIdx.x, wid = tid >> 5, lane = tid & 31;
    int s0 = chunk * 128;

    const __half* pqb = pq + ((size_t)bh * S_LEN + s0) * M_F;

    int arow[4], aseg[4];
    unsigned adst[4];
    #pragma unroll
    for (int i = 0; i < 4; i++) {
        int u = tid + 256 * i;
        arow[i] = u >> 3; aseg[i] = u & 7;
        adst[i] = smu + ND_A_OFF + (unsigned)(arow[i] * ROWB + aseg[i] * 16);
    }

    #pragma unroll
    for (int s = 0; s < 2; s++) {
        const __half* Ac = pqb + s * 64;
        unsigned so = s * TILEB;
        #pragma unroll
        for (int i = 0; i < 4; i++)
            CP16(adst[i] + so, Ac + (size_t)arow[i] * M_F + aseg[i] * 8);
        CP_COMMIT();
    }

    {
        const float* kvb = kvg + (size_t)bh * (M_F * HK);
        for (int i = tid; i < M_F * HK; i += 256) {
            int m = i >> 6, k = i & 63;
            Bsf[k * ND_BSTR + m] = __float2half_rn(kvb[i]);
        }
        z_s[tid] = zg[bh * M_F + tid];
    }

    float acc[2][4][4];
    #pragma unroll
    for (int mi = 0; mi < 2; mi++)
        #pragma unroll
        for (int ni = 0; ni < 4; ni++)
            #pragma unroll
            for (int j = 0; j < 4; j++) acc[mi][ni][j] = 0.f;

    unsigned aoff = (unsigned)((lane & 15) * ROWB + (lane >> 4) * 16);
    unsigned boff = (unsigned)((((lane >> 4) * 8) + (lane & 7)) * ND_BROWB +
                               ((lane >> 3) & 1) * 16);
    unsigned Bsu0 = smu + ND_B_OFF + (unsigned)((wid >> 2) * 32) * ND_BROWB + boff;

    int drow = tid >> 1, dhf = tid & 1;
    float dp = 0.f;

    for (int c = 0; c < 4; c++) {
        int p = c & 1;
        CP_WAIT1();
        __syncthreads();

        const __half* As = (const __half*)(sm + ND_A_OFF + p * TILEB);
        unsigned Asu = smu + ND_A_OFF + p * TILEB +
                       (unsigned)((wid & 3) * 32) * ROWB + aoff;
        unsigned Bsu = Bsu0 + (unsigned)(c * 128);

        #pragma unroll
        for (int ks = 0; ks < 4; ks++) {
            unsigned kb = ks * 32;
            unsigned afr[2][4], bfr[4][2];
            #pragma unroll
            for (int mi = 0; mi < 2; mi++)
                ldsm_x4(afr[mi][0], afr[mi][1], afr[mi][2], afr[mi][3],
                        Asu + mi * (16 * ROWB) + kb);
            #pragma unroll
            for (int pr = 0; pr < 2; pr++)
                ldsm_x4(bfr[2*pr][0], bfr[2*pr][1], bfr[2*pr+1][0], bfr[2*pr+1][1],
                        Bsu + pr * (16 * ND_BROWB) + kb);
            #pragma unroll
            for (int mi = 0; mi < 2; mi++)
                #pragma unroll
                for (int ni = 0; ni < 4; ni++)
                    mma_f16(acc[mi][ni], afr[mi], bfr[ni]);
        }

        {
            const __half* ar = As + drow * HSTR + dhf * 32;
            const float* zr = z_s + c * 64 + dhf * 32;
            #pragma unroll
            for (int j = 0; j < 16; j++) {
                float2 f = __half22float2(*(const __half2*)(ar + 2 * j));
                dp += f.x * zr[2 * j] + f.y * zr[2 * j + 1];
            }
        }
        __syncthreads();

        if (c + 2 < 4) {
            const __half* Ac = pqb + (c + 2) * 64;
            unsigned so = p * TILEB;
            #pragma unroll
            for (int i = 0; i < 4; i++)
                CP16(adst[i] + so, Ac + (size_t)arow[i] * M_F + aseg[i] * 8);
        }
        CP_COMMIT();
    }
    CP_WAIT0();
    __syncthreads();

    #pragma unroll
    for (int mi = 0; mi < 2; mi++)
        #pragma unroll
        for (int ni = 0; ni < 4; ni++) {
            int row = (wid & 3) * 32 + mi * 16 + (lane >> 2);
            int col = (wid >> 2) * 32 + ni * 8 + (lane & 3) * 2;
            *(float2*)(stage + row * 68 + col) =
                make_float2(acc[mi][ni][0], acc[mi][ni][1]);
            *(float2*)(stage + (row + 8) * 68 + col) =
                make_float2(acc[mi][ni][2], acc[mi][ni][3]);
        }

    dp += __shfl_xor_sync(0xFFFFFFFFu, dp, 1);
    if (dhf == 0) den_s[drow] = dp;
    __syncthreads();

    #pragma unroll
    for (int i = 0; i < 8; i++) {
        int u = tid + 256 * i;
        int row = u >> 4, c4 = u & 15;
        float4 v = *(const float4*)(stage + row * 68 + c4 * 4);
        float rd = 1.0f / den_s[row];
        __half2 p0 = __floats2half2_rn(v.x * rd, v.y * rd);
        __half2 p1 = __floats2half2_rn(v.z * rd, v.w * rd);
        uint2 w;
        w.x = *(unsigned*)&p0; w.y = *(unsigned*)&p1;
        *(uint2*)(attn + ((size_t)(b * S_LEN + s0 + row)) * D_MOD + h * 64 + c4 * 4) = w;
    }
}

// ---------------- LayerNorm: half input (OUTHALF: write half) ----------------
template<int OUTHALF>
__global__ void ln_kernel(const __half* __restrict__ X, const float* __restrict__ g,
                          const float* __restrict__ bv, void* __restrict__ outv)
{
    int row = blockIdx.x, tid = threadIdx.x;
    uint2 xw = *(const uint2*)(X + (size_t)row * D_MOD + tid * 4);
    float2 f0 = __half22float2(*(__half2*)&xw.x);
    float2 f1 = __half22float2(*(__half2*)&xw.y);
    float4 v = make_float4(f0.x, f0.y, f1.x, f1.y);
    float s = v.x + v.y + v.z + v.w;
    __shared__ float ws[8];
    #pragma unroll
    for (int o = 16; o; o >>= 1) s += __shfl_xor_sync(0xFFFFFFFFu, s, o);
    if ((tid & 31) == 0) ws[tid >> 5] = s;
    __syncthreads();
    float tot = 0.f;
    #pragma unroll
    for (int w = 0; w < 8; w++) tot += ws[w];
    float mu = tot * (1.f / 1024.f);
    float dx = v.x - mu, dy = v.y - mu, dz = v.z - mu, dw = v.w - mu;
    float sqvv = dx*dx + dy*dy + dz*dz + dw*dw;
    __syncthreads();
    #pragma unroll
    for (int o = 16; o; o >>= 1) sqvv += __shfl_xor_sync(0xFFFFFFFFu, sqvv, o);
    if ((tid & 31) == 0) ws[tid >> 5] = sqvv;
    __syncthreads();
    float tot2 = 0.f;
    #pragma unroll
    for (int w = 0; w < 8; w++) tot2 += ws[w];
    float rs = rsqrtf(tot2 * (1.f / 1024.f) + 1e-6f);
    float4 gg = ((const float4*)g)[tid];
    float4 bb = ((const float4*)bv)[tid];
    float o0 = dx*rs*gg.x + bb.x, o1 = dy*rs*gg.y + bb.y;
    float o2 = dz*rs*gg.z + bb.z, o3 = dw*rs*gg.w + bb.w;
    if (OUTHALF) {
        __half2 p0 = __floats2half2_rn(o0, o1);
        __half2 p1 = __floats2half2_rn(o2, o3);
        uint2 w;
        w.x = *(unsigned*)&p0; w.y = *(unsigned*)&p1;
        *(uint2*)((__half*)outv + (size_t)row * D_MOD + tid * 4) = w;
    } else {
        ((float4*)((float*)outv + (size_t)row * D_MOD))[tid] =
            make_float4(o0, o1, o2, o3);
    }
}

// ---------------- orchestration ----------------
extern "C" void kernel_launch(void* const* d_in, const int* in_sizes, int n_in,
                              void* d_out, int out_size)
{
    const float* x     = (const float*)d_in[0];
    const float* wq    = (const float*)d_in[1];
    const float* wk    = (const float*)d_in[2];
    const float* wv    = (const float*)d_in[3];
    const float* wo    = (const float*)d_in[4];
    const float* omega = (const float*)d_in[5];
    const float* ln1g  = (const float*)d_in[6];
    const float* ln1b  = (const float*)d_in[7];
    const float* w1    = (const float*)d_in[8];
    const float* b1    = (const float*)d_in[9];
    const float* w2    = (const float*)d_in[10];
    const float* b2    = (const float*)d_in[11];
    const float* ln2g  = (const float*)d_in[12];
    const float* ln2b  = (const float*)d_in[13];
    float* out = (float*)d_out;

    __half *qk, *v, *xr, *pq, *pk, *attn, *x1, *act, *y;
    float *kv, *z, *kvp;
    __half *wqkvT, *woT, *w1T, *w2T;
    cudaGetSymbolAddress((void**)&qk,   g_qk);
    cudaGetSymbolAddress((void**)&v,    g_v);
    cudaGetSymbolAddress((void**)&xr,   g_xr);
    cudaGetSymbolAddress((void**)&pq,   g_pq);
    cudaGetSymbolAddress((void**)&pk,   g_pk);
    cudaGetSymbolAddress((void**)&kv,   g_kv);
    cudaGetSymbolAddress((void**)&z,    g_z);
    cudaGetSymbolAddress((void**)&kvp,  g_kvp);
    cudaGetSymbolAddress((void**)&attn, g_attn);
    cudaGetSymbolAddress((void**)&y,    g_y);
    cudaGetSymbolAddress((void**)&x1,   g_x1);
    cudaGetSymbolAddress((void**)&act,  g_act);
    cudaGetSymbolAddress((void**)&wqkvT, g_wqkvT);
    cudaGetSymbolAddress((void**)&woT,  g_woT);
    cudaGetSymbolAddress((void**)&w1T,  g_w1T);
    cudaGetSymbolAddress((void**)&w2T,  g_w2T);

    cudaFuncSetAttribute(numden_mma, cudaFuncAttributeMaxDynamicSharedMemorySize, ND_SM);
    cudaFuncSetAttribute(phi_mma, cudaFuncAttributeMaxDynamicSharedMemorySize, PHI_SM);
    cudaFuncSetAttribute(kv_mma, cudaFuncAttributeMaxDynamicSharedMemorySize, KV_SM);
    cudaFuncSetAttribute(tc_gemm<1>, cudaFuncAttributeMaxDynamicSharedMemorySize, SM_DYN);
    cudaFuncSetAttribute(tc_gemm<2>, cudaFuncAttributeMaxDynamicSharedMemorySize, SM_DYN);
    cudaFuncSetAttribute(tc_gemm<3>, cudaFuncAttributeMaxDynamicSharedMemorySize, SM_DYN);
    cudaFuncSetAttribute(tc_gemm<5>, cudaFuncAttributeMaxDynamicSharedMemorySize, SM_DYN);

    dim3 tb(32, 8);
    transpose4_k<<<dim3(32, 32, 4), tb>>>(wq, wk, wv, wo,
        wqkvT, wqkvT + 1024 * 1024, wqkvT + 2 * 1024 * 1024, woT);
    transpose_k<<<dim3(128, 32),  tb>>>(w1, w1T, 1024, 4096);
    transpose_k<<<dim3(32, 128),  tb>>>(w2, w2T, 4096, 1024);
    cvt_half_kernel<<<(N_TOK * D_MOD / 8 + 255) / 256, 256>>>(x, xr, N_TOK * D_MOD / 8);

    dim3 gQKV(3072 / 128, N_TOK / 128);  // (24, 128)
    dim3 gD(D_MOD / 128, N_TOK / 128);   // (8, 128)
    dim3 gF(FF_D / 128, N_TOK / 128);    // (32, 128)

    tc_gemm<5><<<gQKV, 256, SM_DYN>>>(xr, wqkvT, nullptr, nullptr, nullptr,
                                      v, qk, D_MOD, 3072);

    phi_mma<<<4096, 512, PHI_SM>>>(qk, omega, pq, pk);

    kv_mma<<<256, 256, KV_SM>>>(pk, v, kvp);
    kv_reduce<<<64, 256>>>(kvp, kv, z);

    numden_mma<<<2048, 256, ND_SM>>>(pq, kv, z, attn);

    tc_gemm<1><<<gD, 256, SM_DYN>>>(attn, woT, nullptr, x, nullptr, y, nullptr,
                                    D_MOD, D_MOD);
    ln_kernel<1><<<N_TOK, 256>>>(y, ln1g, ln1b, x1);

    tc_gemm<2><<<gF, 256, SM_DYN>>>(x1, w1T, b1, nullptr, nullptr, act, nullptr,
                                    D_MOD, FF_D);
    tc_gemm<3><<<gD, 256, SM_DYN>>>(act, w2T, b2, nullptr, x1, y, nullptr,
                                    FF_D, D_MOD);
    ln_kernel<0><<<N_TOK, 256>>>(y, ln2g, ln2b, out);
}